// round 15
// baseline (speedup 1.0000x reference)
#include <cuda_runtime.h>
#include <math.h>
#include <stdint.h>

#define T_LEN 4096
#define NSIG  4096          // 16 * 256 signals
#define TOPK  7

typedef unsigned long long u64;

// -------- scratch (module-scope device memory; no runtime allocation) -------
__device__ float2 d_tw[T_LEN];                  // e^{-2*pi*i*j/4096} (for recon)
__device__ float2 d_y1[16 * 128 * 4096];        // stage-1 output:
                                                // [b][p][j*256 + t1] = y1[t1, j]
__device__ int    d_pk [NSIG * TOPK];           // selected frequency index k
__device__ float  d_pre[NSIG * TOPK];           // coefficient real = 4*Re(X)/T
__device__ float  d_pim[NSIG * TOPK];           // coefficient imag = 4*Im(X)/T

// W16^e = (cos(pi*e/8), -sin(pi*e/8)), e = 0..9
__constant__ float2 W16C[10] = {
    { 1.0f, 0.0f},
    { 0.92387953251128674f, -0.38268343236508978f},
    { 0.70710678118654752f, -0.70710678118654752f},
    { 0.38268343236508978f, -0.92387953251128674f},
    { 0.0f, -1.0f},
    { 0.0f,  0.0f},   // unused
    {-0.70710678118654752f, -0.70710678118654752f},
    { 0.0f,  0.0f},   // unused
    { 0.0f,  0.0f},   // unused
    {-0.92387953251128674f,  0.38268343236508978f},
};

// ---------------------------------------------------------------------------
// complex helpers
// ---------------------------------------------------------------------------
__device__ __forceinline__ float2 cmul(float2 a, float2 b) {
    return make_float2(a.x * b.x - a.y * b.y, a.x * b.y + a.y * b.x);
}
__device__ __forceinline__ float2 cadd(float2 a, float2 b) { return make_float2(a.x + b.x, a.y + b.y); }
__device__ __forceinline__ float2 csub(float2 a, float2 b) { return make_float2(a.x - b.x, a.y - b.y); }
__device__ __forceinline__ float2 mnegi(float2 a) { return make_float2(a.y, -a.x); }  // -i * a

// packed f32x2 helpers (FFMA2 path — ptxas only emits these via PTX)
__device__ __forceinline__ u64 packp(float lo, float hi) {
    u64 r;
    asm("mov.b64 %0, {%1, %2};" : "=l"(r) : "r"(__float_as_uint(lo)), "r"(__float_as_uint(hi)));
    return r;
}
__device__ __forceinline__ u64 addp(u64 a, u64 b) {
    u64 r; asm("add.rn.f32x2 %0, %1, %2;" : "=l"(r) : "l"(a), "l"(b)); return r;
}
__device__ __forceinline__ u64 fmap(u64 a, u64 b, u64 c) {
    u64 r; asm("fma.rn.f32x2 %0, %1, %2, %3;" : "=l"(r) : "l"(a), "l"(b), "l"(c)); return r;
}
__device__ __forceinline__ u64 negp(u64 a) {
    u64 r; asm("xor.b64 %0, %1, 0x8000000080000000;" : "=l"(r) : "l"(a)); return r;
}
__device__ __forceinline__ u64 sum7(const u64 q[TOPK]) {
    return addp(addp(addp(q[0], q[1]), addp(q[2], q[3])),
                addp(addp(q[4], q[5]), q[6]));
}

// In-place 16-point DFT: two radix-4 passes, NO temp array.
// After the call, Y[j] lives at slot YSLOT(j) = 4*(j&3) + (j>>2).
#define YSLOT(j) (4 * ((j) & 3) + ((j) >> 2))
__device__ __forceinline__ void dft16_ip(float2 v[16]) {
    #pragma unroll
    for (int m = 0; m < 4; m++) {
        float2 a0 = v[m], a1 = v[m + 4], a2 = v[m + 8], a3 = v[m + 12];
        float2 s02 = cadd(a0, a2), d02 = csub(a0, a2);
        float2 s13 = cadd(a1, a3), d13 = csub(a1, a3);
        float2 id  = mnegi(d13);
        v[m]      = cadd(s02, s13);
        v[m + 4]  = cadd(d02, id);
        v[m + 8]  = csub(s02, s13);
        v[m + 12] = csub(d02, id);
    }
    #pragma unroll
    for (int j1 = 1; j1 < 4; j1++)
        #pragma unroll
        for (int m = 1; m < 4; m++)
            v[m + 4 * j1] = cmul(v[m + 4 * j1], W16C[m * j1]);
    #pragma unroll
    for (int g = 0; g < 4; g++) {
        float2 a0 = v[4*g], a1 = v[4*g + 1], a2 = v[4*g + 2], a3 = v[4*g + 3];
        float2 s02 = cadd(a0, a2), d02 = csub(a0, a2);
        float2 s13 = cadd(a1, a3), d13 = csub(a1, a3);
        float2 id  = mnegi(d13);
        v[4*g]     = cadd(s02, s13);
        v[4*g + 1] = cadd(d02, id);
        v[4*g + 2] = csub(s02, s13);
        v[4*g + 3] = csub(d02, id);
    }
}

// ---------------------------------------------------------------------------
// KA: fused transpose + FFT stage 1 (four-step split, t = t1 + 256*t2).
// (unchanged — measured at its DRAM floor, 22us)
// ---------------------------------------------------------------------------
__global__ void __launch_bounds__(256, 4) k_stage1(const float* __restrict__ x) {
    __shared__ float2 s[32 * 145];     // idx = t1l*145 + t2*9 + pl  (max 4637)

    int tx  = threadIdx.x;             // t1-local (lane)
    int ty  = threadIdx.y;             // p-local (warp)
    int tid = ty * 32 + tx;
    int T0  = blockIdx.x * 32;
    int P0  = blockIdx.y * 8;
    int b   = blockIdx.z;

    // side job: fill recon twiddle table (16 blocks x 256 threads)
    if (blockIdx.z == 0 && blockIdx.y < 2) {
        int j = (blockIdx.y * 8 + blockIdx.x) * 256 + tid;
        float sp, cp;
        sincospif(-(float)j * (1.0f / 2048.0f), &sp, &cp);
        d_tw[j] = make_float2(cp, sp);
    }

    // ---- load 32 t1 x 16 t2 x 8 p tile, coalesced over p ----
    {
        const float2* x2 = (const float2*)x;
        int lp   = tid & 7;            // p within tile
        int lrow = tid >> 3;           // 0..31
        #pragma unroll
        for (int it = 0; it < 16; it++) {
            int row = lrow + it * 32;  // 0..511 = (t1l, t2)
            int t1l = row & 31;
            int t2  = row >> 5;
            s[t1l * 145 + t2 * 9 + lp] =
                x2[((size_t)b * 4096 + T0 + t1l + 256 * t2) * 128 + P0 + lp];
        }
    }
    __syncthreads();

    // ---- compute: thread (t1 = T0+tx, p = P0+ty) ----
    float2 v[16];
    #pragma unroll
    for (int t2 = 0; t2 < 16; t2++)
        v[t2] = s[tx * 145 + t2 * 9 + ty];     // lanes stride 145 (odd) - no conflicts
    dft16_ip(v);

    int t1 = T0 + tx;
    float2 w1;
    { float sp, cp; sincospif(-(float)t1 * (1.0f / 2048.0f), &sp, &cp); w1 = make_float2(cp, sp); }

    float2* yt = d_y1 + ((size_t)b * 128 + P0 + ty) * 4096 + t1;
    yt[0] = v[YSLOT(0)];
    float2 pw = w1;
    #pragma unroll
    for (int j = 1; j < 16; j++) {
        yt[j * 256] = cmul(v[YSLOT(j)], pw);   // lanes = t1 -> 256B coalesced
        pw = cmul(pw, w1);
    }
}

// ---------------------------------------------------------------------------
// KB: FFT stages 2+3 + magnitude + top-7. Block owns one d-pair.
// EXACT revert to the 80.4us R12 version (256,4).
// ---------------------------------------------------------------------------
__global__ void __launch_bounds__(256, 4) k_fft2() {
    extern __shared__ char smraw[];
    float2* sY = (float2*)smraw;                 // 4352 float2 (34816 B)
    float*  cv = (float*)(smraw + 34816);        // 8 floats
    int*    ck = (int*)  (smraw + 34816 + 32);   // 8 ints
    int*    kb = (int*)  (smraw + 34816 + 64);   // 2 ints (winner broadcast)

    int tid = threadIdx.x;
    int b   = blockIdx.x >> 7;       // 16 batches
    int p   = blockIdx.x & 127;      // d-pair: channels 2p, 2p+1

    const float2* yt = d_y1 + ((size_t)b * 128 + p) * 4096;

    float2 v[16];

    // ---- stage 2: thread (j2 = tid>>4, bb = tid&15) ----
    {
        int j2 = tid >> 4, bb = tid & 15;
        #pragma unroll
        for (int c = 0; c < 16; c++)
            v[c] = yt[j2 * 256 + c * 16 + bb];   // y1[16c+bb][j2], coalesced
        dft16_ip(v);
        float2 w2;
        { float sp, cp; sincospif(-(float)bb * (1.0f / 128.0f), &sp, &cp); w2 = make_float2(cp, sp); }
        int base = j2 * 272 + bb;
        float2 pw = w2;
        sY[base] = v[YSLOT(0)];
        #pragma unroll
        for (int i = 1; i < 16; i++) {
            sY[base + i * 17] = cmul(v[YSLOT(i)], pw);
            pw = cmul(pw, w2);
        }
    }
    __syncthreads();

    // ---- stage 3: read own set into regs, sync, scatter spectrum ----
    {
        int j = tid >> 4, i = tid & 15;
        #pragma unroll
        for (int bb = 0; bb < 16; bb++) v[bb] = sY[j * 272 + i * 17 + bb];
        dft16_ip(v);
        __syncthreads();
        // X[k], k = j+16i+256l, stored at k + (k>>4) = j + 17i + 272l
        #pragma unroll
        for (int l = 0; l < 16; l++)
            sY[j + 17 * i + 272 * l] = v[YSLOT(l)];
    }
    __syncthreads();

    // ---- top-7 on squared magnitudes, register-resident ----
    int s    = tid >> 7;
    int lid  = tid & 127;
    int wid  = tid >> 5;
    int lane = tid & 31;

    float mv[16];
    #pragma unroll
    for (int i = 0; i < 16; i++) {
        int k = 1 + lid + 128 * i;
        float m2 = -1.0f;
        if (k < 2048) {
            float2 Z1 = sY[k + (k >> 4)];
            int k2 = 4096 - k;
            float2 Z2 = sY[k2 + (k2 >> 4)];
            float xr, xi;
            if (s == 0) { xr = Z1.x + Z2.x; xi = Z1.y - Z2.y; }
            else        { xr = Z1.y + Z2.y; xi = Z2.x - Z1.x; }
            m2 = xr * xr + xi * xi;     // 4*|X|^2 (monotone in |X|)
        }
        mv[i] = m2;
    }

    float bv = -2.0f; int bk = 1 << 30;
    #pragma unroll
    for (int i = 0; i < 16; i++)
        if (mv[i] > bv) { bv = mv[i]; bk = 1 + lid + 128 * i; }

    for (int r = 0; r < TOPK; r++) {
        float rv = bv; int rk = bk;
        #pragma unroll
        for (int off = 16; off; off >>= 1) {
            float ov = __shfl_down_sync(0xffffffffu, rv, off);
            int   ok = __shfl_down_sync(0xffffffffu, rk, off);
            if (ov > rv || (ov == rv && ok < rk)) { rv = ov; rk = ok; }
        }
        if (lane == 0) { cv[wid] = rv; ck[wid] = rk; }
        __syncthreads();
        if (lid == 0) {
            float Bv = cv[s * 4]; int Bk = ck[s * 4];
            #pragma unroll
            for (int w = 1; w < 4; w++) {
                float ov = cv[s * 4 + w]; int ok = ck[s * 4 + w];
                if (ov > Bv || (ov == Bv && ok < Bk)) { Bv = ov; Bk = ok; }
            }
            int k = Bk;
            float2 Z1 = sY[k + (k >> 4)];
            int k2 = 4096 - k;
            float2 Z2 = sY[k2 + (k2 >> 4)];
            float Xr, Xi;
            if (s == 0) { Xr = 0.5f * (Z1.x + Z2.x); Xi = 0.5f * (Z1.y - Z2.y); }
            else        { Xr = 0.5f * (Z1.y + Z2.y); Xi = 0.5f * (Z2.x - Z1.x); }
            int sig = b * 256 + 2 * p + s;
            d_pk [sig * TOPK + r] = k;
            d_pre[sig * TOPK + r] = Xr * (4.0f / 4096.0f);
            d_pim[sig * TOPK + r] = Xi * (4.0f / 4096.0f);
            kb[s] = k;                  // broadcast winner
        }
        __syncthreads();
        if (r + 1 < TOPK) {
            int rel = kb[s] - 1 - lid;
            if (rel >= 0 && rel < 2048 && (rel & 127) == 0) {
                int slot = rel >> 7;
                #pragma unroll
                for (int i = 0; i < 16; i++)
                    if (i == slot) mv[i] = -1.0f;
                bv = -2.0f; bk = 1 << 30;
                #pragma unroll
                for (int i = 0; i < 16; i++)
                    if (mv[i] > bv) { bv = mv[i]; bk = 1 + lid + 128 * i; }
            }
            __syncthreads();
        }
    }
}

// ---------------------------------------------------------------------------
// K2: packed-f32x2 reconstruction. Lane owns a d-PAIR (channels 2dp, 2dp+1).
// Chebyshev recurrence on sign-transformed q_n = sigma_n * p_n with
// sigma = (+,+,-,-) period 4:  even steps q0 = fma(-c2, q1, q0),
// odd steps q1 = fma(c2, q0, q1) — pure FMA, no per-step negation.
// Outputs at n = 2,3 (mod 4) get one packed sign flip of the final sum.
// Stores are STG.64, coalesced (32 lanes x 8B = 256B line).
// block (32,8); thread does 64 time steps (stride 8); grid (4,16,8).
// ---------------------------------------------------------------------------
__global__ void __launch_bounds__(256) k_recon(float* __restrict__ out) {
    int tx = threadIdx.x, ty = threadIdx.y;
    int dp  = blockIdx.x * 32 + tx;      // d-pair: channels 2dp, 2dp+1
    int b   = blockIdx.y;
    int t0  = blockIdx.z * 512 + ty;

    u64 q0[TOPK], q1[TOPK], c2[TOPK], nc2[TOPK];
    #pragma unroll
    for (int j = 0; j < TOPK; j++) {
        float p0c[2], p1c[2], c2c[2];
        #pragma unroll
        for (int c = 0; c < 2; c++) {
            int sig = b * 256 + 2 * dp + c;
            int   k  = d_pk [sig * TOPK + j];
            float cr = d_pre[sig * TOPK + j];
            float ci = d_pim[sig * TOPK + j];
            float2 w0 = d_tw[(k * t0) & 4095];        // (cos, -sin) of w*t0
            p0c[c] = cr * w0.x + ci * w0.y;           // Re(C * e^{i w t0})
            float2 w1 = d_tw[(k * (t0 + 8)) & 4095];
            p1c[c] = cr * w1.x + ci * w1.y;
            c2c[c] = 2.0f * d_tw[(8 * k) & 4095].x;   // 2*cos(8w)
        }
        q0[j]  = packp(p0c[0], p0c[1]);
        q1[j]  = packp(p1c[0], p1c[1]);
        c2[j]  = packp(c2c[0], c2c[1]);
        nc2[j] = negp(c2[j]);
    }

    u64* po = (u64*)(out + ((size_t)b * 4096 + t0) * 256) + dp;
    po[0]    = sum7(q0);       // n = 0 (sigma +)
    po[1024] = sum7(q1);       // n = 1 (sigma +); 8*256 floats = 1024 u64

    // n = 2..61 in blocks of 4 (pattern -,-,+,+), then epilogue n = 62,63 (-,-)
    int n = 2;
    #pragma unroll 1
    for (int it = 0; it < 15; it++, n += 4) {
        #pragma unroll
        for (int j = 0; j < TOPK; j++) q0[j] = fmap(nc2[j], q1[j], q0[j]);
        po[(size_t)n * 1024] = negp(sum7(q0));
        #pragma unroll
        for (int j = 0; j < TOPK; j++) q1[j] = fmap(c2[j], q0[j], q1[j]);
        po[(size_t)(n + 1) * 1024] = negp(sum7(q1));
        #pragma unroll
        for (int j = 0; j < TOPK; j++) q0[j] = fmap(nc2[j], q1[j], q0[j]);
        po[(size_t)(n + 2) * 1024] = sum7(q0);
        #pragma unroll
        for (int j = 0; j < TOPK; j++) q1[j] = fmap(c2[j], q0[j], q1[j]);
        po[(size_t)(n + 3) * 1024] = sum7(q1);
    }
    #pragma unroll
    for (int j = 0; j < TOPK; j++) q0[j] = fmap(nc2[j], q1[j], q0[j]);
    po[(size_t)62 * 1024] = negp(sum7(q0));
    #pragma unroll
    for (int j = 0; j < TOPK; j++) q1[j] = fmap(c2[j], q0[j], q1[j]);
    po[(size_t)63 * 1024] = negp(sum7(q1));
}

// ---------------------------------------------------------------------------
extern "C" void kernel_launch(void* const* d_in, const int* in_sizes, int n_in,
                              void* d_out, int out_size) {
    (void)in_sizes; (void)n_in; (void)out_size;
    const float* x = (const float*)d_in[0];
    float* out = (float*)d_out;

    cudaFuncSetAttribute(k_fft2, cudaFuncAttributeMaxDynamicSharedMemorySize, 34944);

    dim3 gA(8, 16, 16), bA(32, 8);
    k_stage1<<<gA, bA>>>(x);

    k_fft2<<<2048, 256, 34944>>>();

    dim3 gr(4, 16, 8), br(32, 8);
    k_recon<<<gr, br>>>(out);
}

// round 16
// speedup vs baseline: 1.1019x; 1.1019x over previous
#include <cuda_runtime.h>
#include <math.h>
#include <stdint.h>

#define T_LEN 4096
#define NSIG  4096          // 16 * 256 signals
#define TOPK  7

// -------- scratch (module-scope device memory; no runtime allocation) -------
__device__ float2 d_tw[T_LEN];                  // e^{-2*pi*i*j/4096} (for recon)
__device__ float2 d_y1[16 * 128 * 4096];        // stage-1 output:
                                                // [b][p][j*256 + t1] = y1[t1, j]
__device__ int    d_pk [NSIG * TOPK];           // selected frequency index k
__device__ float  d_pre[NSIG * TOPK];           // coefficient real = 4*Re(X)/T
__device__ float  d_pim[NSIG * TOPK];           // coefficient imag = 4*Im(X)/T

// W16^e = (cos(pi*e/8), -sin(pi*e/8)), e = 0..9
__constant__ float2 W16C[10] = {
    { 1.0f, 0.0f},
    { 0.92387953251128674f, -0.38268343236508978f},
    { 0.70710678118654752f, -0.70710678118654752f},
    { 0.38268343236508978f, -0.92387953251128674f},
    { 0.0f, -1.0f},
    { 0.0f,  0.0f},   // unused
    {-0.70710678118654752f, -0.70710678118654752f},
    { 0.0f,  0.0f},   // unused
    { 0.0f,  0.0f},   // unused
    {-0.92387953251128674f,  0.38268343236508978f},
};

// ---------------------------------------------------------------------------
// complex helpers
// ---------------------------------------------------------------------------
__device__ __forceinline__ float2 cmul(float2 a, float2 b) {
    return make_float2(a.x * b.x - a.y * b.y, a.x * b.y + a.y * b.x);
}
__device__ __forceinline__ float2 cadd(float2 a, float2 b) { return make_float2(a.x + b.x, a.y + b.y); }
__device__ __forceinline__ float2 csub(float2 a, float2 b) { return make_float2(a.x - b.x, a.y - b.y); }
__device__ __forceinline__ float2 mnegi(float2 a) { return make_float2(a.y, -a.x); }  // -i * a

// In-place 16-point DFT: two radix-4 passes, NO temp array.
// After the call, Y[j] lives at slot YSLOT(j) = 4*(j&3) + (j>>2).
#define YSLOT(j) (4 * ((j) & 3) + ((j) >> 2))
__device__ __forceinline__ void dft16_ip(float2 v[16]) {
    #pragma unroll
    for (int m = 0; m < 4; m++) {
        float2 a0 = v[m], a1 = v[m + 4], a2 = v[m + 8], a3 = v[m + 12];
        float2 s02 = cadd(a0, a2), d02 = csub(a0, a2);
        float2 s13 = cadd(a1, a3), d13 = csub(a1, a3);
        float2 id  = mnegi(d13);
        v[m]      = cadd(s02, s13);
        v[m + 4]  = cadd(d02, id);
        v[m + 8]  = csub(s02, s13);
        v[m + 12] = csub(d02, id);
    }
    #pragma unroll
    for (int j1 = 1; j1 < 4; j1++)
        #pragma unroll
        for (int m = 1; m < 4; m++)
            v[m + 4 * j1] = cmul(v[m + 4 * j1], W16C[m * j1]);
    #pragma unroll
    for (int g = 0; g < 4; g++) {
        float2 a0 = v[4*g], a1 = v[4*g + 1], a2 = v[4*g + 2], a3 = v[4*g + 3];
        float2 s02 = cadd(a0, a2), d02 = csub(a0, a2);
        float2 s13 = cadd(a1, a3), d13 = csub(a1, a3);
        float2 id  = mnegi(d13);
        v[4*g]     = cadd(s02, s13);
        v[4*g + 1] = cadd(d02, id);
        v[4*g + 2] = csub(s02, s13);
        v[4*g + 3] = csub(d02, id);
    }
}

// second half of dft16 (twiddle + pass 2) for the interleaved-load path
__device__ __forceinline__ void dft16_finish(float2 v[16]) {
    #pragma unroll
    for (int j1 = 1; j1 < 4; j1++)
        #pragma unroll
        for (int m = 1; m < 4; m++)
            v[m + 4 * j1] = cmul(v[m + 4 * j1], W16C[m * j1]);
    #pragma unroll
    for (int g = 0; g < 4; g++) {
        float2 a0 = v[4*g], a1 = v[4*g + 1], a2 = v[4*g + 2], a3 = v[4*g + 3];
        float2 s02 = cadd(a0, a2), d02 = csub(a0, a2);
        float2 s13 = cadd(a1, a3), d13 = csub(a1, a3);
        float2 id  = mnegi(d13);
        v[4*g]     = cadd(s02, s13);
        v[4*g + 1] = cadd(d02, id);
        v[4*g + 2] = csub(s02, s13);
        v[4*g + 3] = csub(d02, id);
    }
}

// ---------------------------------------------------------------------------
// KA: fused transpose + FFT stage 1 (four-step split, t = t1 + 256*t2).
// (unchanged — measured at its DRAM floor, 22us)
// ---------------------------------------------------------------------------
__global__ void __launch_bounds__(256, 4) k_stage1(const float* __restrict__ x) {
    __shared__ float2 s[32 * 145];     // idx = t1l*145 + t2*9 + pl  (max 4637)

    int tx  = threadIdx.x;             // t1-local (lane)
    int ty  = threadIdx.y;             // p-local (warp)
    int tid = ty * 32 + tx;
    int T0  = blockIdx.x * 32;
    int P0  = blockIdx.y * 8;
    int b   = blockIdx.z;

    // side job: fill recon twiddle table (16 blocks x 256 threads)
    if (blockIdx.z == 0 && blockIdx.y < 2) {
        int j = (blockIdx.y * 8 + blockIdx.x) * 256 + tid;
        float sp, cp;
        sincospif(-(float)j * (1.0f / 2048.0f), &sp, &cp);
        d_tw[j] = make_float2(cp, sp);
    }

    // ---- load 32 t1 x 16 t2 x 8 p tile, coalesced over p ----
    {
        const float2* x2 = (const float2*)x;
        int lp   = tid & 7;            // p within tile
        int lrow = tid >> 3;           // 0..31
        #pragma unroll
        for (int it = 0; it < 16; it++) {
            int row = lrow + it * 32;  // 0..511 = (t1l, t2)
            int t1l = row & 31;
            int t2  = row >> 5;
            s[t1l * 145 + t2 * 9 + lp] =
                x2[((size_t)b * 4096 + T0 + t1l + 256 * t2) * 128 + P0 + lp];
        }
    }
    __syncthreads();

    // ---- compute: thread (t1 = T0+tx, p = P0+ty) ----
    float2 v[16];
    #pragma unroll
    for (int t2 = 0; t2 < 16; t2++)
        v[t2] = s[tx * 145 + t2 * 9 + ty];     // lanes stride 145 (odd) - no conflicts
    dft16_ip(v);

    int t1 = T0 + tx;
    float2 w1;
    { float sp, cp; sincospif(-(float)t1 * (1.0f / 2048.0f), &sp, &cp); w1 = make_float2(cp, sp); }

    float2* yt = d_y1 + ((size_t)b * 128 + P0 + ty) * 4096 + t1;
    yt[0] = v[YSLOT(0)];
    float2 pw = w1;
    #pragma unroll
    for (int j = 1; j < 16; j++) {
        yt[j * 256] = cmul(v[YSLOT(j)], pw);   // lanes = t1 -> 256B coalesced
        pw = cmul(pw, w1);
    }
}

// ---------------------------------------------------------------------------
// KB: FFT stages 2+3 + magnitude + top-7. Block owns one d-pair.
// R12 logic; ONLY change: stage-2 global loads interleaved with radix-4
// pass-1 compute in 4 groups of 4 (compiler fences stop ptxas from hoisting
// all 16 LDG into one front batch). MLP_p1 16 -> 4 cuts the documented
// cross-CTA L1tex-queue spread. Arithmetic order bit-identical.
// ---------------------------------------------------------------------------
__global__ void __launch_bounds__(256, 4) k_fft2() {
    extern __shared__ char smraw[];
    float2* sY = (float2*)smraw;                 // 4352 float2 (34816 B)
    float*  cv = (float*)(smraw + 34816);        // 8 floats
    int*    ck = (int*)  (smraw + 34816 + 32);   // 8 ints
    int*    kb = (int*)  (smraw + 34816 + 64);   // 2 ints (winner broadcast)

    int tid = threadIdx.x;
    int b   = blockIdx.x >> 7;       // 16 batches
    int p   = blockIdx.x & 127;      // d-pair: channels 2p, 2p+1

    const float2* yt = d_y1 + ((size_t)b * 128 + p) * 4096;

    float2 v[16];

    // ---- stage 2: thread (j2 = tid>>4, bb = tid&15) ----
    {
        int j2 = tid >> 4, bb = tid & 15;
        float2 w2;
        { float sp, cp; sincospif(-(float)bb * (1.0f / 128.0f), &sp, &cp); w2 = make_float2(cp, sp); }

        const float2* yb = yt + j2 * 256 + bb;
        // interleaved: group m loads columns {m, m+4, m+8, m+12} and runs
        // its radix-4 pass-1 before the next group's loads (fence-enforced).
        #pragma unroll
        for (int m = 0; m < 4; m++) {
            float2 a0 = yb[(m)      * 16];
            float2 a1 = yb[(m + 4)  * 16];
            float2 a2 = yb[(m + 8)  * 16];
            float2 a3 = yb[(m + 12) * 16];
            float2 s02 = cadd(a0, a2), d02 = csub(a0, a2);
            float2 s13 = cadd(a1, a3), d13 = csub(a1, a3);
            float2 id  = mnegi(d13);
            v[m]      = cadd(s02, s13);
            v[m + 4]  = cadd(d02, id);
            v[m + 8]  = csub(s02, s13);
            v[m + 12] = csub(d02, id);
            asm volatile("" ::: "memory");   // keep next group's LDG below
        }
        dft16_finish(v);

        int base = j2 * 272 + bb;
        float2 pw = w2;
        sY[base] = v[YSLOT(0)];
        #pragma unroll
        for (int i = 1; i < 16; i++) {
            sY[base + i * 17] = cmul(v[YSLOT(i)], pw);
            pw = cmul(pw, w2);
        }
    }
    __syncthreads();

    // ---- stage 3: read own set into regs, sync, scatter spectrum ----
    {
        int j = tid >> 4, i = tid & 15;
        #pragma unroll
        for (int bb = 0; bb < 16; bb++) v[bb] = sY[j * 272 + i * 17 + bb];
        dft16_ip(v);
        __syncthreads();
        // X[k], k = j+16i+256l, stored at k + (k>>4) = j + 17i + 272l
        #pragma unroll
        for (int l = 0; l < 16; l++)
            sY[j + 17 * i + 272 * l] = v[YSLOT(l)];
    }
    __syncthreads();

    // ---- top-7 on squared magnitudes, register-resident ----
    int s    = tid >> 7;
    int lid  = tid & 127;
    int wid  = tid >> 5;
    int lane = tid & 31;

    float mv[16];
    #pragma unroll
    for (int i = 0; i < 16; i++) {
        int k = 1 + lid + 128 * i;
        float m2 = -1.0f;
        if (k < 2048) {
            float2 Z1 = sY[k + (k >> 4)];
            int k2 = 4096 - k;
            float2 Z2 = sY[k2 + (k2 >> 4)];
            float xr, xi;
            if (s == 0) { xr = Z1.x + Z2.x; xi = Z1.y - Z2.y; }
            else        { xr = Z1.y + Z2.y; xi = Z2.x - Z1.x; }
            m2 = xr * xr + xi * xi;     // 4*|X|^2 (monotone in |X|)
        }
        mv[i] = m2;
    }

    float bv = -2.0f; int bk = 1 << 30;
    #pragma unroll
    for (int i = 0; i < 16; i++)
        if (mv[i] > bv) { bv = mv[i]; bk = 1 + lid + 128 * i; }

    for (int r = 0; r < TOPK; r++) {
        float rv = bv; int rk = bk;
        #pragma unroll
        for (int off = 16; off; off >>= 1) {
            float ov = __shfl_down_sync(0xffffffffu, rv, off);
            int   ok = __shfl_down_sync(0xffffffffu, rk, off);
            if (ov > rv || (ov == rv && ok < rk)) { rv = ov; rk = ok; }
        }
        if (lane == 0) { cv[wid] = rv; ck[wid] = rk; }
        __syncthreads();
        if (lid == 0) {
            float Bv = cv[s * 4]; int Bk = ck[s * 4];
            #pragma unroll
            for (int w = 1; w < 4; w++) {
                float ov = cv[s * 4 + w]; int ok = ck[s * 4 + w];
                if (ov > Bv || (ov == Bv && ok < Bk)) { Bv = ov; Bk = ok; }
            }
            int k = Bk;
            float2 Z1 = sY[k + (k >> 4)];
            int k2 = 4096 - k;
            float2 Z2 = sY[k2 + (k2 >> 4)];
            float Xr, Xi;
            if (s == 0) { Xr = 0.5f * (Z1.x + Z2.x); Xi = 0.5f * (Z1.y - Z2.y); }
            else        { Xr = 0.5f * (Z1.y + Z2.y); Xi = 0.5f * (Z2.x - Z1.x); }
            int sig = b * 256 + 2 * p + s;
            d_pk [sig * TOPK + r] = k;
            d_pre[sig * TOPK + r] = Xr * (4.0f / 4096.0f);
            d_pim[sig * TOPK + r] = Xi * (4.0f / 4096.0f);
            kb[s] = k;                  // broadcast winner
        }
        __syncthreads();
        if (r + 1 < TOPK) {
            int rel = kb[s] - 1 - lid;
            if (rel >= 0 && rel < 2048 && (rel & 127) == 0) {
                int slot = rel >> 7;
                #pragma unroll
                for (int i = 0; i < 16; i++)
                    if (i == slot) mv[i] = -1.0f;
                bv = -2.0f; bk = 1 << 30;
                #pragma unroll
                for (int i = 0; i < 16; i++)
                    if (mv[i] > bv) { bv = mv[i]; bk = 1 + lid + 128 * i; }
            }
            __syncthreads();
        }
    }
}

// ---------------------------------------------------------------------------
// K2: reconstruction via Chebyshev 3-term recurrence (step = 8 samples)
//     EXACT R12 scalar version (measured 19.2us; packed variant regressed).
// ---------------------------------------------------------------------------
__global__ void __launch_bounds__(256) k_recon(float* __restrict__ out) {
    int tx = threadIdx.x, ty = threadIdx.y;
    int d   = blockIdx.x * 32 + tx;
    int b   = blockIdx.y;
    int t0  = blockIdx.z * 1024 + ty;
    int sig = b * 256 + d;

    float p0[TOPK], p1[TOPK], c2[TOPK];
    #pragma unroll
    for (int j = 0; j < TOPK; j++) {
        int   k  = d_pk [sig * TOPK + j];
        float cr = d_pre[sig * TOPK + j];
        float ci = d_pim[sig * TOPK + j];
        float2 w0 = d_tw[(k * t0) & 4095];        // (cos, -sin) of w*t0
        p0[j] = cr * w0.x + ci * w0.y;            // Re(C * e^{i w t0})
        float2 w1 = d_tw[(k * (t0 + 8)) & 4095];
        p1[j] = cr * w1.x + ci * w1.y;
        c2[j] = 2.0f * d_tw[(8 * k) & 4095].x;    // 2*cos(8w)
    }

    float* po = out + ((size_t)b * 4096 + t0) * 256 + d;
    {
        float a0 = 0.0f, a1 = 0.0f;
        #pragma unroll
        for (int j = 0; j < TOPK; j++) { a0 += p0[j]; a1 += p1[j]; }
        po[0]    = a0;
        po[2048] = a1;    // 8 * 256
    }

    #pragma unroll 4
    for (int n = 2; n < 128; n += 2) {
        float s0 = 0.0f, s1 = 0.0f;
        #pragma unroll
        for (int j = 0; j < TOPK; j++) {
            p0[j] = c2[j] * p1[j] - p0[j];
            s0 += p0[j];
        }
        po[(size_t)n * 2048] = s0;
        #pragma unroll
        for (int j = 0; j < TOPK; j++) {
            p1[j] = c2[j] * p0[j] - p1[j];
            s1 += p1[j];
        }
        po[(size_t)(n + 1) * 2048] = s1;
    }
}

// ---------------------------------------------------------------------------
extern "C" void kernel_launch(void* const* d_in, const int* in_sizes, int n_in,
                              void* d_out, int out_size) {
    (void)in_sizes; (void)n_in; (void)out_size;
    const float* x = (const float*)d_in[0];
    float* out = (float*)d_out;

    cudaFuncSetAttribute(k_fft2, cudaFuncAttributeMaxDynamicSharedMemorySize, 34944);

    dim3 gA(8, 16, 16), bA(32, 8);
    k_stage1<<<gA, bA>>>(x);

    k_fft2<<<2048, 256, 34944>>>();

    dim3 gr(8, 16, 4), br(32, 8);
    k_recon<<<gr, br>>>(out);
}